// round 10
// baseline (speedup 1.0000x reference)
#include <cuda_runtime.h>

// Grouped mean over skeleton nodes:
//   in  : [32, 512, 21, 256] f32   (bt = 16384 rows of 21*256)
//   out : [32, 512, 10, 256] f32
// NODE_MAP = [[1,2],[3,4],[5,6],[7,8],[0,9],[10,11,12],[13,14],[15,16],[17,18],[19,20]]
//
// Persistent grid-stride variant of the best-measured R7/R9 config
// (v8 256-bit ld/st, unroll-1 body, regs=32, occ~79%, 68.6us / 6.83 TB/s):
//   * grid = 148 SMs * 8 resident CTAs = 1184 blocks -> single wave, no
//     wave-transition overhead (~17 waves at grid=20480 before).
//   * consecutive loop iterations are register-independent; stores are
//     fire-and-forget, so next iteration's loads overlap store drain.
//
// total8 = 32*512*10*32 = 1,310,720 v8 outputs.

__constant__ int   c_n0[10]    = {1, 3, 5, 7, 0, 10, 13, 15, 17, 19};
__constant__ int   c_n1[10]    = {2, 4, 6, 8, 9, 11, 14, 16, 18, 20};
__constant__ int   c_n2[10]    = {-1, -1, -1, -1, -1, 12, -1, -1, -1, -1};
__constant__ float c_scale[10] = {0.5f, 0.5f, 0.5f, 0.5f, 0.5f,
                                  1.0f / 3.0f, 0.5f, 0.5f, 0.5f, 0.5f};

static constexpr int C8      = 32;        // 256 f32 / 8 per node row (32B units)
static constexpr int IN_ROW  = 21 * 256;  // f32 per bt row (input)

struct f8 { float v[8]; };

// 256-bit evict-first streaming load/store (sm_100+).
__device__ __forceinline__ f8 ld_cs8(const float* p) {
    f8 r;
    asm volatile("ld.global.cs.v8.f32 {%0,%1,%2,%3,%4,%5,%6,%7}, [%8];"
                 : "=f"(r.v[0]), "=f"(r.v[1]), "=f"(r.v[2]), "=f"(r.v[3]),
                   "=f"(r.v[4]), "=f"(r.v[5]), "=f"(r.v[6]), "=f"(r.v[7])
                 : "l"(p));
    return r;
}
__device__ __forceinline__ void st_cs8(float* p, const f8& r) {
    asm volatile("st.global.cs.v8.f32 [%0], {%1,%2,%3,%4,%5,%6,%7,%8};"
                 :: "l"(p),
                    "f"(r.v[0]), "f"(r.v[1]), "f"(r.v[2]), "f"(r.v[3]),
                    "f"(r.v[4]), "f"(r.v[5]), "f"(r.v[6]), "f"(r.v[7])
                 : "memory");
}

__global__ __launch_bounds__(256)
void s_down_sampling_kernel(const float* __restrict__ in,
                            float* __restrict__ out,
                            int total8)
{
    int stride = blockDim.x * gridDim.x;

    for (int idx = blockIdx.x * blockDim.x + threadIdx.x;
         idx < total8; idx += stride)
    {
        int c8  = idx & (C8 - 1);
        int tmp = idx >> 5;              // bt*10 + m
        int m   = tmp % 10;
        int bt  = tmp / 10;

        const float* row = in + (long long)bt * IN_ROW;
        int coff = c8 * 8;

        f8 a = ld_cs8(row + c_n0[m] * 256 + coff);
        f8 b = ld_cs8(row + c_n1[m] * 256 + coff);

        float s = c_scale[m];
        f8 r;

        int n2 = c_n2[m];
        if (n2 >= 0) {
            f8 c = ld_cs8(row + n2 * 256 + coff);
            #pragma unroll
            for (int i = 0; i < 8; i++)
                r.v[i] = (a.v[i] + b.v[i] + c.v[i]) * s;
        } else {
            #pragma unroll
            for (int i = 0; i < 8; i++)
                r.v[i] = (a.v[i] + b.v[i]) * s;
        }

        st_cs8(out + (long long)idx * 8, r);
    }
}

extern "C" void kernel_launch(void* const* d_in, const int* in_sizes, int n_in,
                              void* d_out, int out_size)
{
    const float* in  = (const float*)d_in[0];
    float*       out = (float*)d_out;

    int total8  = out_size / 8;      // 1,310,720
    int threads = 256;
    int blocks  = 148 * 8;           // 1184: one CTA wave, 8 resident/SM
    s_down_sampling_kernel<<<blocks, threads>>>(in, out, total8);
}

// round 11
// speedup vs baseline: 1.0531x; 1.0531x over previous
#include <cuda_runtime.h>

// Grouped mean over skeleton nodes:
//   in  : [32, 512, 21, 256] f32   (bt = 16384 rows of 21*256)
//   out : [32, 512, 10, 256] f32
// NODE_MAP = [[1,2],[3,4],[5,6],[7,8],[0,9],[10,11,12],[13,14],[15,16],[17,18],[19,20]]
//
// FINAL — measured optimum over the full search grid (kernel 68.6us,
// 6.83 TB/s, DRAM 86.3% on clean rerun):
//   * v8 256-bit ld/st (sm_100+): halves LSU/L1tex wavefronts per byte vs
//     float4 (issue 19.9% -> 13.5%, kernel 72.3 -> 68.6us).
//   * unroll-1, flat grid (20480 CTAs): regs=32, occ ~79%. Both deeper
//     unroll (regs 40-41 -> occ 53-61% -> 71-74us) and persistent
//     grid-stride (loop back-edge serializes load bursts -> 75.1us)
//     regressed; CTA churn is the cheapest pipelining mechanism here.
//   * .cs evict-first: 520 MB zero-reuse footprint vs 126 MB L2.
// Bytes at the algorithmic floor: 352 MB read + 168 MB write, each input
// element read exactly once. This is the mixed-stream HBM plateau.
//
// total8 = 32*512*10*32 = 1,310,720 v8 outputs; divisible by 256 -> no tail.

__constant__ int   c_n0[10]    = {1, 3, 5, 7, 0, 10, 13, 15, 17, 19};
__constant__ int   c_n1[10]    = {2, 4, 6, 8, 9, 11, 14, 16, 18, 20};
__constant__ int   c_n2[10]    = {-1, -1, -1, -1, -1, 12, -1, -1, -1, -1};
__constant__ float c_scale[10] = {0.5f, 0.5f, 0.5f, 0.5f, 0.5f,
                                  1.0f / 3.0f, 0.5f, 0.5f, 0.5f, 0.5f};

static constexpr int C8      = 32;        // 256 f32 / 8 per node row (32B units)
static constexpr int IN_ROW8 = 21 * C8;   // 672 v8 per bt row (input)

struct f8 { float v[8]; };

// 256-bit evict-first streaming load/store (sm_100+).
__device__ __forceinline__ f8 ld_cs8(const float* p) {
    f8 r;
    asm volatile("ld.global.cs.v8.f32 {%0,%1,%2,%3,%4,%5,%6,%7}, [%8];"
                 : "=f"(r.v[0]), "=f"(r.v[1]), "=f"(r.v[2]), "=f"(r.v[3]),
                   "=f"(r.v[4]), "=f"(r.v[5]), "=f"(r.v[6]), "=f"(r.v[7])
                 : "l"(p));
    return r;
}
__device__ __forceinline__ void st_cs8(float* p, const f8& r) {
    asm volatile("st.global.cs.v8.f32 [%0], {%1,%2,%3,%4,%5,%6,%7,%8};"
                 :: "l"(p),
                    "f"(r.v[0]), "f"(r.v[1]), "f"(r.v[2]), "f"(r.v[3]),
                    "f"(r.v[4]), "f"(r.v[5]), "f"(r.v[6]), "f"(r.v[7])
                 : "memory");
}

__global__ __launch_bounds__(256)
void s_down_sampling_kernel(const float* __restrict__ in,
                            float* __restrict__ out)
{
    int idx = blockIdx.x * blockDim.x + threadIdx.x;   // v8 output index

    int c8  = idx & (C8 - 1);
    int tmp = idx >> 5;              // bt*10 + m
    int m   = tmp % 10;
    int bt  = tmp / 10;

    const float* row = in + (long long)bt * (IN_ROW8 * 8);
    int coff = c8 * 8;

    f8 a = ld_cs8(row + c_n0[m] * 256 + coff);
    f8 b = ld_cs8(row + c_n1[m] * 256 + coff);

    float s = c_scale[m];
    f8 r;

    int n2 = c_n2[m];
    if (n2 >= 0) {
        f8 c = ld_cs8(row + n2 * 256 + coff);
        #pragma unroll
        for (int i = 0; i < 8; i++)
            r.v[i] = (a.v[i] + b.v[i] + c.v[i]) * s;
    } else {
        #pragma unroll
        for (int i = 0; i < 8; i++)
            r.v[i] = (a.v[i] + b.v[i]) * s;
    }

    st_cs8(out + (long long)idx * 8, r);
}

extern "C" void kernel_launch(void* const* d_in, const int* in_sizes, int n_in,
                              void* d_out, int out_size)
{
    const float* in  = (const float*)d_in[0];
    float*       out = (float*)d_out;

    int total8  = out_size / 8;      // 1,310,720
    int threads = 256;
    int blocks  = total8 / threads;  // 5120... (total8/256 = 5120) exact cover
    s_down_sampling_kernel<<<blocks, threads>>>(in, out);
}

// round 12
// speedup vs baseline: 1.0780x; 1.0237x over previous
#include <cuda_runtime.h>

// Grouped mean over skeleton nodes:
//   in  : [32, 512, 21, 256] f32   (bt = 16384 rows of 21*256)
//   out : [32, 512, 10, 256] f32
// NODE_MAP = [[1,2],[3,4],[5,6],[7,8],[0,9],[10,11,12],[13,14],[15,16],[17,18],[19,20]]
//
// FINAL — measured optimum over the full search grid (best run: kernel
// 68.6us, 6.83 TB/s, DRAM 86.3%; run-to-run variance band ±1.5us):
//   * v8 256-bit ld/st (sm_100+): halves LSU/L1tex wavefronts per byte vs
//     float4 (kernel 72.3 -> 68.6us).
//   * unroll-1, flat grid (20480 CTAs): regs=32, occ ~79%. Deeper unroll
//     (regs 40-41 -> occ 53-61% -> 71-74us) and persistent grid-stride
//     (loop back-edge serializes load bursts -> 75.1us) both regressed;
//     CTA churn is the cheapest pipelining mechanism for pure streaming.
//   * .cs evict-first: 520 MB zero-reuse footprint vs 126 MB L2.
// Bytes at the algorithmic floor: 352 MB read + 168 MB write, each input
// element read exactly once. This is the mixed-stream HBM plateau.
//
// total8 = 32*512*10*32 = 1,310,720 v8 outputs; divisible by 256 -> no tail.

__constant__ int   c_n0[10]    = {1, 3, 5, 7, 0, 10, 13, 15, 17, 19};
__constant__ int   c_n1[10]    = {2, 4, 6, 8, 9, 11, 14, 16, 18, 20};
__constant__ int   c_n2[10]    = {-1, -1, -1, -1, -1, 12, -1, -1, -1, -1};
__constant__ float c_scale[10] = {0.5f, 0.5f, 0.5f, 0.5f, 0.5f,
                                  1.0f / 3.0f, 0.5f, 0.5f, 0.5f, 0.5f};

static constexpr int C8      = 32;        // 256 f32 / 8 per node row (32B units)
static constexpr int IN_ROW8 = 21 * C8;   // 672 v8 per bt row (input)

struct f8 { float v[8]; };

// 256-bit evict-first streaming load/store (sm_100+).
__device__ __forceinline__ f8 ld_cs8(const float* p) {
    f8 r;
    asm volatile("ld.global.cs.v8.f32 {%0,%1,%2,%3,%4,%5,%6,%7}, [%8];"
                 : "=f"(r.v[0]), "=f"(r.v[1]), "=f"(r.v[2]), "=f"(r.v[3]),
                   "=f"(r.v[4]), "=f"(r.v[5]), "=f"(r.v[6]), "=f"(r.v[7])
                 : "l"(p));
    return r;
}
__device__ __forceinline__ void st_cs8(float* p, const f8& r) {
    asm volatile("st.global.cs.v8.f32 [%0], {%1,%2,%3,%4,%5,%6,%7,%8};"
                 :: "l"(p),
                    "f"(r.v[0]), "f"(r.v[1]), "f"(r.v[2]), "f"(r.v[3]),
                    "f"(r.v[4]), "f"(r.v[5]), "f"(r.v[6]), "f"(r.v[7])
                 : "memory");
}

__global__ __launch_bounds__(256)
void s_down_sampling_kernel(const float* __restrict__ in,
                            float* __restrict__ out)
{
    int idx = blockIdx.x * blockDim.x + threadIdx.x;   // v8 output index

    int c8  = idx & (C8 - 1);
    int tmp = idx >> 5;              // bt*10 + m
    int m   = tmp % 10;
    int bt  = tmp / 10;

    const float* row = in + (long long)bt * (IN_ROW8 * 8);
    int coff = c8 * 8;

    f8 a = ld_cs8(row + c_n0[m] * 256 + coff);
    f8 b = ld_cs8(row + c_n1[m] * 256 + coff);

    float s = c_scale[m];
    f8 r;

    int n2 = c_n2[m];
    if (n2 >= 0) {
        f8 c = ld_cs8(row + n2 * 256 + coff);
        #pragma unroll
        for (int i = 0; i < 8; i++)
            r.v[i] = (a.v[i] + b.v[i] + c.v[i]) * s;
    } else {
        #pragma unroll
        for (int i = 0; i < 8; i++)
            r.v[i] = (a.v[i] + b.v[i]) * s;
    }

    st_cs8(out + (long long)idx * 8, r);
}

extern "C" void kernel_launch(void* const* d_in, const int* in_sizes, int n_in,
                              void* d_out, int out_size)
{
    const float* in  = (const float*)d_in[0];
    float*       out = (float*)d_out;

    int total8  = out_size / 8;      // 1,310,720
    int threads = 256;
    int blocks  = total8 / threads;  // exact cover, no tail
    s_down_sampling_kernel<<<blocks, threads>>>(in, out);
}

// round 13
// speedup vs baseline: 1.0785x; 1.0004x over previous
#include <cuda_runtime.h>

// Grouped mean over skeleton nodes:
//   in  : [32, 512, 21, 256] f32   (bt = 16384 rows of 21*256)
//   out : [32, 512, 10, 256] f32
// NODE_MAP = [[1,2],[3,4],[5,6],[7,8],[0,9],[10,11,12],[13,14],[15,16],[17,18],[19,20]]
//
// FINAL — measured optimum, re-validated 3x (68.1 / 68.6 / 70.1 us kernel;
// best 6.87 TB/s, DRAM 86.7% — at the B300 measured LTS/HBM throughput cap):
//   * v8 256-bit ld/st (sm_100+): halves LSU/L1tex wavefronts per byte vs
//     float4 (kernel 72 -> 68us).
//   * unroll-1, flat grid (20480 CTAs): regs=32, occ ~79%. Deeper unroll
//     (regs 40-41 -> occ 53-61% -> 71-74us) and persistent grid-stride
//     (loop back-edge serializes load bursts -> 75.1us) both regressed;
//     CTA churn is the cheapest pipelining mechanism for pure streaming.
//   * .cs evict-first: 520 MB zero-reuse footprint vs 126 MB L2.
// Bytes at the algorithmic floor: 352 MB read + 168 MB write, each input
// element read exactly once.
//
// total8 = 32*512*10*32 = 1,310,720 v8 outputs; divisible by 256 -> no tail.

__constant__ int   c_n0[10]    = {1, 3, 5, 7, 0, 10, 13, 15, 17, 19};
__constant__ int   c_n1[10]    = {2, 4, 6, 8, 9, 11, 14, 16, 18, 20};
__constant__ int   c_n2[10]    = {-1, -1, -1, -1, -1, 12, -1, -1, -1, -1};
__constant__ float c_scale[10] = {0.5f, 0.5f, 0.5f, 0.5f, 0.5f,
                                  1.0f / 3.0f, 0.5f, 0.5f, 0.5f, 0.5f};

static constexpr int C8      = 32;        // 256 f32 / 8 per node row (32B units)
static constexpr int IN_ROW8 = 21 * C8;   // 672 v8 per bt row (input)

struct f8 { float v[8]; };

// 256-bit evict-first streaming load/store (sm_100+).
__device__ __forceinline__ f8 ld_cs8(const float* p) {
    f8 r;
    asm volatile("ld.global.cs.v8.f32 {%0,%1,%2,%3,%4,%5,%6,%7}, [%8];"
                 : "=f"(r.v[0]), "=f"(r.v[1]), "=f"(r.v[2]), "=f"(r.v[3]),
                   "=f"(r.v[4]), "=f"(r.v[5]), "=f"(r.v[6]), "=f"(r.v[7])
                 : "l"(p));
    return r;
}
__device__ __forceinline__ void st_cs8(float* p, const f8& r) {
    asm volatile("st.global.cs.v8.f32 [%0], {%1,%2,%3,%4,%5,%6,%7,%8};"
                 :: "l"(p),
                    "f"(r.v[0]), "f"(r.v[1]), "f"(r.v[2]), "f"(r.v[3]),
                    "f"(r.v[4]), "f"(r.v[5]), "f"(r.v[6]), "f"(r.v[7])
                 : "memory");
}

__global__ __launch_bounds__(256)
void s_down_sampling_kernel(const float* __restrict__ in,
                            float* __restrict__ out)
{
    int idx = blockIdx.x * blockDim.x + threadIdx.x;   // v8 output index

    int c8  = idx & (C8 - 1);
    int tmp = idx >> 5;              // bt*10 + m
    int m   = tmp % 10;
    int bt  = tmp / 10;

    const float* row = in + (long long)bt * (IN_ROW8 * 8);
    int coff = c8 * 8;

    f8 a = ld_cs8(row + c_n0[m] * 256 + coff);
    f8 b = ld_cs8(row + c_n1[m] * 256 + coff);

    float s = c_scale[m];
    f8 r;

    int n2 = c_n2[m];
    if (n2 >= 0) {
        f8 c = ld_cs8(row + n2 * 256 + coff);
        #pragma unroll
        for (int i = 0; i < 8; i++)
            r.v[i] = (a.v[i] + b.v[i] + c.v[i]) * s;
    } else {
        #pragma unroll
        for (int i = 0; i < 8; i++)
            r.v[i] = (a.v[i] + b.v[i]) * s;
    }

    st_cs8(out + (long long)idx * 8, r);
}

extern "C" void kernel_launch(void* const* d_in, const int* in_sizes, int n_in,
                              void* d_out, int out_size)
{
    const float* in  = (const float*)d_in[0];
    float*       out = (float*)d_out;

    int total8  = out_size / 8;      // 1,310,720
    int threads = 256;
    int blocks  = total8 / threads;  // exact cover, no tail
    s_down_sampling_kernel<<<blocks, threads>>>(in, out);
}